// round 1
// baseline (speedup 1.0000x reference)
#include <cuda_runtime.h>

#define BB   32
#define CC   3072
#define HWD  784
#define KK   11
#define NCLS 200
#define NCHUNK 24
#define CCH  128           // CC / NCHUNK

typedef unsigned long long u64;

// ---- scratch (static device memory; no allocations) ----
__device__ float g_pab[(size_t)NCHUNK * BB * KK * HWD];  // partial ab, 26.5 MB
__device__ float g_asq[KK];
__device__ float g_fsT[CC * BB];                          // sum_k afm, transposed [c][b]

// ---- packed f32x2 helpers (sm_10x) ----
__device__ __forceinline__ u64 fma2(u64 a, u64 b, u64 c) {
    u64 d; asm("fma.rn.f32x2 %0, %1, %2, %3;" : "=l"(d) : "l"(a), "l"(b), "l"(c)); return d;
}
__device__ __forceinline__ u64 add2(u64 a, u64 b) {
    u64 d; asm("add.rn.f32x2 %0, %1, %2;" : "=l"(d) : "l"(a), "l"(b)); return d;
}
__device__ __forceinline__ u64 pk(float lo, float hi) {
    u64 d; asm("mov.b64 %0, {%1, %2};" : "=l"(d) : "f"(lo), "f"(hi)); return d;
}
__device__ __forceinline__ void upk(u64 v, float& lo, float& hi) {
    asm("mov.b64 {%0, %1}, %2;" : "=f"(lo), "=f"(hi) : "l"(v));
}

// ================= kernel 0: a_sq[k] = sum_c w_land[k,c]^2 =================
__global__ void k_asq(const float* __restrict__ w_land) {
    int w = threadIdx.x >> 5, lane = threadIdx.x & 31;   // 11 warps
    float s = 0.f;
    for (int c = lane; c < CC; c += 32) { float v = w_land[w * CC + c]; s += v * v; }
    #pragma unroll
    for (int o = 16; o; o >>= 1) s += __shfl_down_sync(0xffffffffu, s, o);
    if (lane == 0) g_asq[w] = s;
}

// ====== kernel 1: partial ab[chunk][b][k][p] over 128-channel chunks =======
// grid (NCHUNK, B), block 224. Each thread owns two float2 pixel slots
// (4 pixels) so 11 smem weight loads amortize over 22 packed FMAs.
__global__ void __launch_bounds__(224) k_pab(const float* __restrict__ x,
                                             const float* __restrict__ w_land) {
    const int chunk = blockIdx.x, b = blockIdx.y;
    const int c0 = chunk * CCH;
    __shared__ u64 w2[CCH * KK];
    for (int i = threadIdx.x; i < CCH * KK; i += blockDim.x) {
        int c = i / KK, k = i - c * KK;
        float v = w_land[k * CC + c0 + c];
        w2[i] = pk(v, v);
    }
    __syncthreads();
    const int t = threadIdx.x;
    if (t >= 196) return;                         // 196 threads x 2 slots = 392 float2 = 784 px
    const u64* xp = (const u64*)(x + ((size_t)b * CC + c0) * HWD);
    const int sA = t, sB = t + 196;
    u64 aA[KK], aB[KK];
    #pragma unroll
    for (int k = 0; k < KK; k++) { aA[k] = 0ull; aB[k] = 0ull; }
    #pragma unroll 2
    for (int c = 0; c < CCH; c++) {
        u64 xa = xp[c * 392 + sA];
        u64 xb = xp[c * 392 + sB];
        #pragma unroll
        for (int k = 0; k < KK; k++) {
            u64 w = w2[c * KK + k];
            aA[k] = fma2(xa, w, aA[k]);
            aB[k] = fma2(xb, w, aB[k]);
        }
    }
    u64* po = (u64*)(g_pab + ((size_t)(chunk * BB + b)) * KK * HWD);
    #pragma unroll
    for (int k = 0; k < KK; k++) {
        po[k * 392 + sA] = aA[k];
        po[k * 392 + sB] = aB[k];
    }
}

// ===== kernel 2: reduce chunks, softmax over k (b_sq cancels), attn ========
__global__ void k_soft(float* __restrict__ out_maps, float* __restrict__ out_attn) {
    const int b = blockIdx.x;
    __shared__ float asq[KK];
    if (threadIdx.x < KK) asq[threadIdx.x] = g_asq[threadIdx.x];
    __syncthreads();
    float attn[KK];
    #pragma unroll
    for (int k = 0; k < KK; k++) attn[k] = 0.f;
    for (int p = threadIdx.x; p < HWD; p += blockDim.x) {
        float v[KK];
        #pragma unroll
        for (int k = 0; k < KK; k++) {
            float s = 0.f;
            #pragma unroll 4
            for (int ch = 0; ch < NCHUNK; ch++)
                s += g_pab[(((size_t)ch * BB + b) * KK + k) * HWD + p];
            v[k] = 2.f * s - asq[k];
        }
        float m = v[0];
        #pragma unroll
        for (int k = 1; k < KK; k++) m = fmaxf(m, v[k]);
        float tot = 0.f;
        #pragma unroll
        for (int k = 0; k < KK; k++) { v[k] = __expf(v[k] - m); tot += v[k]; }
        float inv = 1.f / tot;
        #pragma unroll
        for (int k = 0; k < KK; k++) {
            float mp = v[k] * inv;
            out_maps[((size_t)b * KK + k) * HWD + p] = mp;
            attn[k] += mp;
        }
    }
    __shared__ float red[32];
    int lane = threadIdx.x & 31, wid = threadIdx.x >> 5;
    #pragma unroll
    for (int k = 0; k < KK; k++) {
        float v = attn[k];
        #pragma unroll
        for (int o = 16; o; o >>= 1) v += __shfl_down_sync(0xffffffffu, v, o);
        if (lane == 0) red[wid] = v;
        __syncthreads();
        if (threadIdx.x == 0) {
            float s = 0.f;
            for (int w = 0; w < (int)(blockDim.x >> 5); w++) s += red[w];
            out_attn[b * KK + k] = s;
        }
        __syncthreads();
    }
}

// ===== kernel 3: afm[b,c,k] = (sum_p maps[k,p] x[c,p])/784 * mod[c,k] ======
// grid (16, B), block 256. Each warp processes two channel-PAIRS at once
// (4 channels, packed f32x2 over the channel dimension); maps broadcast
// from static smem. Also writes per-channel k-sums (transposed) for scores.
__global__ void __launch_bounds__(256) k_feat(const float* __restrict__ x,
                                              const float* __restrict__ maps,
                                              const float* __restrict__ modulation,
                                              float* __restrict__ out_afm) {
    const int b = blockIdx.y;
    __shared__ float msm[KK * HWD];                       // 34.5 KB
    const float* mb = maps + (size_t)b * KK * HWD;
    for (int i = threadIdx.x; i < KK * HWD; i += blockDim.x) msm[i] = mb[i];
    __syncthreads();

    const int warp = threadIdx.x >> 5, lane = threadIdx.x & 31;
    const int pbase = blockIdx.x * 96;                    // 96 channel-pairs per CTA
    const float inv = 1.f / 784.f;
    for (int i = 0; i < 6; i++) {
        int pairA = pbase + warp + 8 * (2 * i);
        int pairB = pbase + warp + 8 * (2 * i + 1);
        int ca = 2 * pairA, cb = 2 * pairB;
        const float* xa0 = x + ((size_t)b * CC + ca) * HWD;
        const float* xb0 = x + ((size_t)b * CC + cb) * HWD;
        u64 aA[KK], aB[KK];
        #pragma unroll
        for (int k = 0; k < KK; k++) { aA[k] = 0ull; aB[k] = 0ull; }
        for (int p = lane; p < HWD; p += 32) {
            u64 xa = pk(xa0[p], xa0[p + HWD]);            // channels ca, ca+1
            u64 xb = pk(xb0[p], xb0[p + HWD]);            // channels cb, cb+1
            #pragma unroll
            for (int k = 0; k < KK; k++) {
                float m = msm[k * HWD + p];
                u64 m2 = pk(m, m);
                aA[k] = fma2(xa, m2, aA[k]);
                aB[k] = fma2(xb, m2, aB[k]);
            }
        }
        #pragma unroll
        for (int k = 0; k < KK; k++) {
            #pragma unroll
            for (int o = 16; o; o >>= 1) {
                aA[k] = add2(aA[k], __shfl_down_sync(0xffffffffu, aA[k], o));
                aB[k] = add2(aB[k], __shfl_down_sync(0xffffffffu, aB[k], o));
            }
        }
        if (lane == 0) {
            float s0 = 0.f, s1 = 0.f, s2 = 0.f, s3 = 0.f;
            #pragma unroll
            for (int k = 0; k < KK; k++) {
                float v0, v1, v2, v3;
                upk(aA[k], v0, v1); upk(aB[k], v2, v3);
                v0 = v0 * inv * modulation[ca * KK + k];
                v1 = v1 * inv * modulation[(ca + 1) * KK + k];
                v2 = v2 * inv * modulation[cb * KK + k];
                v3 = v3 * inv * modulation[(cb + 1) * KK + k];
                out_afm[((size_t)b * CC + ca) * KK + k]     = v0;
                out_afm[((size_t)b * CC + ca + 1) * KK + k] = v1;
                out_afm[((size_t)b * CC + cb) * KK + k]     = v2;
                out_afm[((size_t)b * CC + cb + 1) * KK + k] = v3;
                s0 += v0; s1 += v1; s2 += v2; s3 += v3;
            }
            g_fsT[ca * BB + b]       = s0;
            g_fsT[(ca + 1) * BB + b] = s1;
            g_fsT[cb * BB + b]       = s2;
            g_fsT[(cb + 1) * BB + b] = s3;
        }
    }
}

// ===== kernel 4: scores[b,n] = sum_c fsT[c][b] * w_cls[n,c] ================
// grid 50, block 256: four n's per CTA, 64 threads per n over c, all 32 b's
// packed as 16 f32x2 accumulators.
__global__ void __launch_bounds__(256) k_scores(const float* __restrict__ w_cls,
                                                float* __restrict__ out_scores) {
    const int n0 = blockIdx.x * 4;
    const int g = threadIdx.x >> 6;                       // 0..3
    const int l = threadIdx.x & 63;
    const int n = n0 + g;
    u64 acc[16];
    #pragma unroll
    for (int j = 0; j < 16; j++) acc[j] = 0ull;
    for (int c = l; c < CC; c += 64) {
        float wv = w_cls[(size_t)n * CC + c];
        u64 wp = pk(wv, wv);
        const u64* fr = (const u64*)(g_fsT + c * BB);
        #pragma unroll
        for (int j = 0; j < 16; j++) acc[j] = fma2(fr[j], wp, acc[j]);
    }
    __shared__ u64 gt[8][16];
    int lane = threadIdx.x & 31, wid = threadIdx.x >> 5;
    #pragma unroll
    for (int j = 0; j < 16; j++) {
        u64 v = acc[j];
        #pragma unroll
        for (int o = 16; o; o >>= 1) v = add2(v, __shfl_down_sync(0xffffffffu, v, o));
        if (lane == 0) gt[wid][j] = v;
    }
    __syncthreads();
    if (threadIdx.x < 64) {
        int gg = threadIdx.x >> 4, j = threadIdx.x & 15;
        u64 v = add2(gt[2 * gg][j], gt[2 * gg + 1][j]);
        float f0, f1; upk(v, f0, f1);
        out_scores[(2 * j) * NCLS + n0 + gg]     = f0;    // b = 2j
        out_scores[(2 * j + 1) * NCLS + n0 + gg] = f1;    // b = 2j+1
    }
}

// ============================== launch =====================================
extern "C" void kernel_launch(void* const* d_in, const int* in_sizes, int n_in,
                              void* d_out, int out_size) {
    const float* x          = (const float*)d_in[0];
    const float* w_land     = (const float*)d_in[1];
    const float* modulation = (const float*)d_in[2];
    const float* w_cls      = (const float*)d_in[3];
    float* out        = (float*)d_out;
    float* out_afm    = out;                               // (B,C,K)  1081344
    float* out_scores = out + 1081344;                     // (B,NC)      6400
    float* out_maps   = out + 1087744;                     // (B,K,H,W) 275968
    float* out_attn   = out + 1363712;                     // (B,K)        352

    k_asq<<<1, 352>>>(w_land);
    k_pab<<<dim3(NCHUNK, BB), 224>>>(x, w_land);
    k_soft<<<BB, 256>>>(out_maps, out_attn);
    k_feat<<<dim3(16, BB), 256>>>(x, out_maps, modulation, out_afm);
    k_scores<<<50, 256>>>(w_cls, out_scores);
}

// round 2
// speedup vs baseline: 1.5754x; 1.5754x over previous
#include <cuda_runtime.h>

#define BB   32
#define CC   3072
#define HWD  784
#define KK   11
#define NCLS 200
#define NCHUNK 24
#define CCH  128           // CC / NCHUNK

typedef unsigned long long u64;

// ---- scratch (static device memory; no allocations) ----
__device__ float g_pab[(size_t)NCHUNK * BB * KK * HWD];  // partial ab, 26.5 MB
__device__ float g_asq[KK];
__device__ float g_fsT[CC * BB];                          // sum_k afm, transposed [c][b]
__device__ float g_attnp[4 * BB * KK];                    // attn partials per quarter

// ---- packed f32x2 helpers (sm_10x) ----
__device__ __forceinline__ u64 fma2(u64 a, u64 b, u64 c) {
    u64 d; asm("fma.rn.f32x2 %0, %1, %2, %3;" : "=l"(d) : "l"(a), "l"(b), "l"(c)); return d;
}
__device__ __forceinline__ u64 add2(u64 a, u64 b) {
    u64 d; asm("add.rn.f32x2 %0, %1, %2;" : "=l"(d) : "l"(a), "l"(b)); return d;
}
__device__ __forceinline__ u64 pk(float lo, float hi) {
    u64 d; asm("mov.b64 %0, {%1, %2};" : "=l"(d) : "f"(lo), "f"(hi)); return d;
}
__device__ __forceinline__ void upk(u64 v, float& lo, float& hi) {
    asm("mov.b64 {%0, %1}, %2;" : "=f"(lo), "=f"(hi) : "l"(v));
}

// ================= kernel 0: a_sq[k] = sum_c w_land[k,c]^2 =================
__global__ void k_asq(const float* __restrict__ w_land) {
    int w = threadIdx.x >> 5, lane = threadIdx.x & 31;   // 11 warps
    float s = 0.f;
    for (int c = lane; c < CC; c += 32) { float v = w_land[w * CC + c]; s += v * v; }
    #pragma unroll
    for (int o = 16; o; o >>= 1) s += __shfl_down_sync(0xffffffffu, s, o);
    if (lane == 0) g_asq[w] = s;
}

// ====== kernel 1: partial ab[chunk][b][k][p] over 128-channel chunks =======
// grid (NCHUNK, B), block 224 (196 active). Each thread owns one float4 pixel
// slot (4 px). Weights prepacked in smem as k-pair float4 (w0,w0,w1,w1) so the
// k-loop costs 6 broadcast LDS.128 + 24 FMA2 per channel.
__global__ void __launch_bounds__(224) k_pab(const float* __restrict__ x,
                                             const float* __restrict__ w_land) {
    const int chunk = blockIdx.x, b = blockIdx.y;
    const int c0 = chunk * CCH;
    __shared__ float4 w4[CCH * 6];
    for (int i = threadIdx.x; i < CCH * 6; i += 224) {
        int c = i / 6, kp = i - c * 6;
        float v0 = w_land[(2 * kp) * CC + c0 + c];
        float v1 = (2 * kp + 1 < KK) ? w_land[(2 * kp + 1) * CC + c0 + c] : 0.f;
        w4[i] = make_float4(v0, v0, v1, v1);
    }
    __syncthreads();
    const int t = threadIdx.x;
    if (t >= 196) return;
    const float4* xr = (const float4*)(x + ((size_t)b * CC + c0) * HWD);

    u64 a0[12], a1[12];
    #pragma unroll
    for (int k = 0; k < 12; k++) { a0[k] = 0ull; a1[k] = 0ull; }

    float4 xv = xr[t];
    #pragma unroll 2
    for (int c = 0; c < CCH; c++) {
        int cn = (c + 1 < CCH) ? c + 1 : c;
        float4 xn = xr[cn * 196 + t];                 // prefetch next channel
        u64 x01 = pk(xv.x, xv.y), x23 = pk(xv.z, xv.w);
        #pragma unroll
        for (int kp = 0; kp < 6; kp++) {
            float4 wv = w4[c * 6 + kp];               // broadcast LDS.128
            u64 wlo = pk(wv.x, wv.y), whi = pk(wv.z, wv.w);
            a0[2 * kp]     = fma2(x01, wlo, a0[2 * kp]);
            a1[2 * kp]     = fma2(x23, wlo, a1[2 * kp]);
            a0[2 * kp + 1] = fma2(x01, whi, a0[2 * kp + 1]);
            a1[2 * kp + 1] = fma2(x23, whi, a1[2 * kp + 1]);
        }
        xv = xn;
    }
    float4* po = (float4*)(g_pab + ((size_t)(chunk * BB + b)) * KK * HWD);
    #pragma unroll
    for (int k = 0; k < KK; k++) {
        float l0, h0, l2, h2;
        upk(a0[k], l0, h0); upk(a1[k], l2, h2);
        po[k * 196 + t] = make_float4(l0, h0, l2, h2);
    }
}

// ===== kernel 2: reduce chunks, softmax over k (b_sq cancels) ==============
// grid (4, B), block 64 (49 active): each thread one float4 pixel slot.
__global__ void __launch_bounds__(64) k_soft(float* __restrict__ out_maps) {
    const int q = blockIdx.x, b = blockIdx.y;
    const int t = threadIdx.x;
    const int slot = q * 49 + t;
    const bool act = (t < 49);
    const int lane = t & 31, wid = t >> 5;

    float a[KK];
    #pragma unroll
    for (int k = 0; k < KK; k++) a[k] = 0.f;

    if (act) {
        const float4* pb = (const float4*)g_pab;
        float4 v[KK];
        #pragma unroll
        for (int k = 0; k < KK; k++) {
            float4 s = make_float4(0.f, 0.f, 0.f, 0.f);
            #pragma unroll 6
            for (int ch = 0; ch < NCHUNK; ch++) {
                float4 u = pb[((size_t)(ch * BB + b) * KK + k) * 196 + slot];
                s.x += u.x; s.y += u.y; s.z += u.z; s.w += u.w;
            }
            float aq = g_asq[k];
            v[k] = make_float4(2.f * s.x - aq, 2.f * s.y - aq,
                               2.f * s.z - aq, 2.f * s.w - aq);
        }
        float4 m = v[0];
        #pragma unroll
        for (int k = 1; k < KK; k++) {
            m.x = fmaxf(m.x, v[k].x); m.y = fmaxf(m.y, v[k].y);
            m.z = fmaxf(m.z, v[k].z); m.w = fmaxf(m.w, v[k].w);
        }
        float4 tot = make_float4(0.f, 0.f, 0.f, 0.f);
        #pragma unroll
        for (int k = 0; k < KK; k++) {
            v[k].x = __expf(v[k].x - m.x); tot.x += v[k].x;
            v[k].y = __expf(v[k].y - m.y); tot.y += v[k].y;
            v[k].z = __expf(v[k].z - m.z); tot.z += v[k].z;
            v[k].w = __expf(v[k].w - m.w); tot.w += v[k].w;
        }
        float4 inv = make_float4(1.f / tot.x, 1.f / tot.y, 1.f / tot.z, 1.f / tot.w);
        float4* mo = (float4*)(out_maps + (size_t)b * KK * HWD);
        #pragma unroll
        for (int k = 0; k < KK; k++) {
            float4 mp = make_float4(v[k].x * inv.x, v[k].y * inv.y,
                                    v[k].z * inv.z, v[k].w * inv.w);
            mo[k * 196 + slot] = mp;
            a[k] = mp.x + mp.y + mp.z + mp.w;
        }
    }
    __shared__ float red[2][KK];
    #pragma unroll
    for (int k = 0; k < KK; k++) {
        float s = a[k];
        #pragma unroll
        for (int o = 16; o; o >>= 1) s += __shfl_down_sync(0xffffffffu, s, o);
        if (lane == 0) red[wid][k] = s;
    }
    __syncthreads();
    if (t < KK) g_attnp[(q * BB + b) * KK + t] = red[0][t] + red[1][t];
}

// ===== kernel 3: afm[b,c,k] = (sum_p maps[k,p] x[c,p])/784 * mod[c,k] ======
// grid (12, B), block 128. Lane owns channels (c, c+32) fully; pixels iterate
// as float4. Maps read via warp-uniform broadcast LDS.128. No cross-lane
// reduction. Also finishes attn (blockIdx.x==0) and writes g_fsT for scores.
__global__ void __launch_bounds__(128) k_feat(const float* __restrict__ x,
                                              const float* __restrict__ maps,
                                              const float* __restrict__ modulation,
                                              float* __restrict__ out_afm,
                                              float* __restrict__ out_attn) {
    const int b = blockIdx.y;
    __shared__ float4 msm4[KK * 196];                     // 34.5 KB
    const float4* mb = (const float4*)(maps + (size_t)b * KK * HWD);
    for (int i = threadIdx.x; i < KK * 196; i += 128) msm4[i] = mb[i];
    __syncthreads();

    if (blockIdx.x == 0 && threadIdx.x < KK) {
        float s = 0.f;
        #pragma unroll
        for (int q = 0; q < 4; q++) s += g_attnp[(q * BB + b) * KK + threadIdx.x];
        out_attn[b * KK + threadIdx.x] = s;
    }

    const int warp = threadIdx.x >> 5, lane = threadIdx.x & 31;
    const int c0 = blockIdx.x * 256 + warp * 64 + lane;
    const int c1 = c0 + 32;
    const float4* xr0 = (const float4*)(x + ((size_t)b * CC + c0) * HWD);
    const float4* xr1 = (const float4*)(x + ((size_t)b * CC + c1) * HWD);

    u64 a0[KK], a1[KK];
    #pragma unroll
    for (int k = 0; k < KK; k++) { a0[k] = 0ull; a1[k] = 0ull; }

    float4 xv0 = xr0[0], xv1 = xr1[0];
    #pragma unroll 2
    for (int j = 0; j < 196; j++) {
        int jn = (j + 1 < 196) ? j + 1 : j;
        float4 xn0 = xr0[jn], xn1 = xr1[jn];              // prefetch
        u64 x001 = pk(xv0.x, xv0.y), x023 = pk(xv0.z, xv0.w);
        u64 x101 = pk(xv1.x, xv1.y), x123 = pk(xv1.z, xv1.w);
        #pragma unroll
        for (int k = 0; k < KK; k++) {
            float4 mv = msm4[k * 196 + j];                // broadcast LDS.128
            u64 m01 = pk(mv.x, mv.y), m23 = pk(mv.z, mv.w);
            a0[k] = fma2(x001, m01, a0[k]);
            a0[k] = fma2(x023, m23, a0[k]);
            a1[k] = fma2(x101, m01, a1[k]);
            a1[k] = fma2(x123, m23, a1[k]);
        }
        xv0 = xn0; xv1 = xn1;
    }

    const float inv = 1.f / 784.f;
    float fs0 = 0.f, fs1 = 0.f;
    #pragma unroll
    for (int k = 0; k < KK; k++) {
        float lo, hi;
        upk(a0[k], lo, hi);
        float v0 = (lo + hi) * inv * modulation[c0 * KK + k];
        out_afm[((size_t)b * CC + c0) * KK + k] = v0; fs0 += v0;
        upk(a1[k], lo, hi);
        float v1 = (lo + hi) * inv * modulation[c1 * KK + k];
        out_afm[((size_t)b * CC + c1) * KK + k] = v1; fs1 += v1;
    }
    g_fsT[c0 * BB + b] = fs0;
    g_fsT[c1 * BB + b] = fs1;
}

// ===== kernel 4: scores[b,n] = sum_c fsT[c][b] * w_cls[n,c] ================
__global__ void __launch_bounds__(256) k_scores(const float* __restrict__ w_cls,
                                                float* __restrict__ out_scores) {
    const int n0 = blockIdx.x * 4;
    const int g = threadIdx.x >> 6;                       // 0..3
    const int l = threadIdx.x & 63;
    const int n = n0 + g;
    u64 acc[16];
    #pragma unroll
    for (int j = 0; j < 16; j++) acc[j] = 0ull;
    for (int c = l; c < CC; c += 64) {
        float wv = w_cls[(size_t)n * CC + c];
        u64 wp = pk(wv, wv);
        const u64* fr = (const u64*)(g_fsT + c * BB);
        #pragma unroll
        for (int j = 0; j < 16; j++) acc[j] = fma2(fr[j], wp, acc[j]);
    }
    __shared__ u64 gt[8][16];
    int lane = threadIdx.x & 31, wid = threadIdx.x >> 5;
    #pragma unroll
    for (int j = 0; j < 16; j++) {
        u64 v = acc[j];
        #pragma unroll
        for (int o = 16; o; o >>= 1) v = add2(v, __shfl_down_sync(0xffffffffu, v, o));
        if (lane == 0) gt[wid][j] = v;
    }
    __syncthreads();
    if (threadIdx.x < 64) {
        int gg = threadIdx.x >> 4, j = threadIdx.x & 15;
        u64 v = add2(gt[2 * gg][j], gt[2 * gg + 1][j]);
        float f0, f1; upk(v, f0, f1);
        out_scores[(2 * j) * NCLS + n0 + gg]     = f0;    // b = 2j
        out_scores[(2 * j + 1) * NCLS + n0 + gg] = f1;    // b = 2j+1
    }
}

// ============================== launch =====================================
extern "C" void kernel_launch(void* const* d_in, const int* in_sizes, int n_in,
                              void* d_out, int out_size) {
    const float* x          = (const float*)d_in[0];
    const float* w_land     = (const float*)d_in[1];
    const float* modulation = (const float*)d_in[2];
    const float* w_cls      = (const float*)d_in[3];
    float* out        = (float*)d_out;
    float* out_afm    = out;                               // (B,C,K)  1081344
    float* out_scores = out + 1081344;                     // (B,NC)      6400
    float* out_maps   = out + 1087744;                     // (B,K,H,W) 275968
    float* out_attn   = out + 1363712;                     // (B,K)        352

    k_asq<<<1, 352>>>(w_land);
    k_pab<<<dim3(NCHUNK, BB), 224>>>(x, w_land);
    k_soft<<<dim3(4, BB), 64>>>(out_maps);
    k_feat<<<dim3(12, BB), 128>>>(x, out_maps, modulation, out_afm, out_attn);
    k_scores<<<50, 256>>>(w_cls, out_scores);
}